// round 13
// baseline (speedup 1.0000x reference)
#include <cuda_runtime.h>
#include <cuda_fp16.h>
#include <cstdint>
#include <math.h>

// Problem constants
#define BB 32
#define CC 128
#define VV 8192
#define NUMEL (BB*CC*16*16)   // 1048576

// ---------------- device scratch (no allocs allowed) ----------------
__device__ float g_frest[NUMEL];
__device__ float g_fhat[NUMEL];
__device__ float g_esq[VV];
__device__ unsigned long long g_packed[VV]; // (ordered_score<<32)|idx
__device__ float g_h[NUMEL];
__device__ float g_loss;
// fp16 split operands, deduplicated K=256 layout [hi(128)|lo(128)].
// logical K=384 products: rest_hi*emb_hi + rest_lo*emb_hi + rest_hi*emb_lo
__device__ __align__(16) __half g_embP[(size_t)VV * 256];
__device__ __align__(16) __half g_restP[(size_t)VV * 256];
// conv operands:
//  hT[b][sp=y*16+x][plane]: plane<128 = hi(h[ci]), 128..255 = lo(h[ci])
__device__ __align__(16) __half g_hT[(size_t)BB * 256 * 256];
//  wP[phi][tap][cout][256]: [hi|lo]
__device__ __align__(16) __half g_wP[(size_t)4 * 9 * 128 * 256];

__device__ __forceinline__ uint32_t smem_to_u32(const void* p) {
    uint32_t a;
    asm("{ .reg .u64 t; cvta.to.shared.u64 t, %1; cvt.u32.u64 %0, t; }" : "=r"(a) : "l"(p));
    return a;
}
__device__ __forceinline__ void ldsm_x4(uint32_t& r0, uint32_t& r1, uint32_t& r2, uint32_t& r3,
                                        uint32_t addr) {
    asm volatile("ldmatrix.sync.aligned.m8n8.x4.shared.b16 {%0,%1,%2,%3}, [%4];"
                 : "=r"(r0), "=r"(r1), "=r"(r2), "=r"(r3) : "r"(addr));
}
__device__ __forceinline__ void mma16816(float* d, const uint32_t* a, const uint32_t* b) {
    asm volatile("mma.sync.aligned.m16n8k16.row.col.f32.f16.f16.f32 "
                 "{%0,%1,%2,%3}, {%4,%5,%6,%7}, {%8,%9}, {%0,%1,%2,%3};"
                 : "+f"(d[0]), "+f"(d[1]), "+f"(d[2]), "+f"(d[3])
                 : "r"(a[0]), "r"(a[1]), "r"(a[2]), "r"(a[3]), "r"(b[0]), "r"(b[1]));
}
#define CP_ASYNC16(dst, src) \
    asm volatile("cp.async.cg.shared.global [%0], [%1], 16;" :: "r"(dst), "l"(src))
#define CP_ASYNC16_P(dst, src, sz) \
    asm volatile("cp.async.cg.shared.global [%0], [%1], 16, %2;" :: "r"(dst), "l"(src), "r"(sz))
#define CP_COMMIT() asm volatile("cp.async.commit_group;" ::: "memory")
#define CP_WAIT1()  asm volatile("cp.async.wait_group 1;" ::: "memory")
#define CP_WAIT0()  asm volatile("cp.async.wait_group 0;" ::: "memory")

// ---------------- init ----------------
__global__ void k_init(const float* __restrict__ f) {
    int i = blockIdx.x * 256 + threadIdx.x;
    g_frest[i] = f[i];
    g_fhat[i] = 0.f;
    if (i == 0) g_loss = 0.f;
}

// ---------------- prep emb: esq + fp16 split [hi|lo] ----------------
__global__ void k_prep_emb(const float* __restrict__ emb) {
    int code = blockIdx.x * 8 + (threadIdx.x >> 5);
    int lane = threadIdx.x & 31;
    float4 v = *(const float4*)(emb + (size_t)code * CC + lane * 4);
    float s = v.x*v.x + v.y*v.y + v.z*v.z + v.w*v.w;
    #pragma unroll
    for (int o = 16; o; o >>= 1) s += __shfl_xor_sync(0xffffffffu, s, o);
    if (lane == 0) g_esq[code] = s;

    __half h0 = __float2half(v.x), h1 = __float2half(v.y);
    __half h2 = __float2half(v.z), h3 = __float2half(v.w);
    __half l0 = __float2half(v.x - __half2float(h0));
    __half l1 = __float2half(v.y - __half2float(h1));
    __half l2 = __float2half(v.z - __half2float(h2));
    __half l3 = __float2half(v.w - __half2float(h3));
    __half2 hA = __halves2half2(h0, h1), hB = __halves2half2(h2, h3);
    __half2 lA = __halves2half2(l0, l1), lB = __halves2half2(l2, l3);
    __half2* base = (__half2*)(g_embP + (size_t)code * 256);
    int c2 = lane * 2;
    base[c2] = hA; base[c2 + 1] = hB;            // hi
    base[64 + c2] = lA; base[64 + c2 + 1] = lB;  // lo
}

// ---------------- prep weights: wP[phi][tap][cout][256] fp16 [hi|lo] ----------------
__global__ void k_prep_w(const float* __restrict__ phi_w) {
    int id = blockIdx.x;            // 4*9*128
    int cout = id & 127;
    int tap = (id >> 7) % 9;
    int phi = id / (9 * 128);
    int ci = threadIdx.x;
    float w = phi_w[(((size_t)phi * 128 + cout) * 128 + ci) * 9 + tap];
    __half hi = __float2half(w);
    __half lo = __float2half(w - __half2float(hi));
    __half* dst = g_wP + (((size_t)phi * 9 + tap) * 128 + cout) * 256;
    dst[ci] = hi; dst[128 + ci] = lo;
}

// ---------------- pool (warp-per-output, for s>=8) ----------------
__global__ void k_pool_warp(int pn, int s, int ls, float inv) {
    int w = (blockIdx.x * 256 + threadIdx.x) >> 5;  // w = n*128 + c
    int lane = threadIdx.x & 31;
    int n = w >> 7, c = w & 127;
    int pp = pn * pn;
    int b = n / pp;
    int rem = n - b * pp;
    int py = rem / pn, px = rem - py * pn;
    const float* base = g_frest + ((size_t)(b * CC + c)) * 256 + (py * s) * 16 + px * s;
    int s2 = s * s;
    float sum = 0.f;
    for (int e = lane; e < s2; e += 32)
        sum += base[(e >> ls) * 16 + (e & (s - 1))];
    #pragma unroll
    for (int o = 16; o; o >>= 1) sum += __shfl_xor_sync(0xffffffffu, sum, o);
    if (lane == 0) {
        float m = sum * inv;
        __half hi = __float2half(m);
        __half lo = __float2half(m - __half2float(hi));
        __half* dst = g_restP + (size_t)n * 256;
        dst[c] = hi; dst[128 + c] = lo;
        if (c == 0) g_packed[n] = ~0ull;
    }
}

// ---------------- pool (thread-per-output, for s<=4) ----------------
__global__ void k_pool(int pn, int s, int N) {
    int n = blockIdx.x;
    int c = threadIdx.x;
    int b = n / (pn * pn);
    int rem = n - b * pn * pn;
    int py = rem / pn, px = rem - py * pn;
    const float* base = g_frest + ((size_t)(b * CC + c)) * 256;
    float sum = 0.f;
    for (int dy = 0; dy < s; dy++)
        for (int dx = 0; dx < s; dx++)
            sum += base[(py * s + dy) * 16 + (px * s + dx)];
    float m = sum * (1.f / (float)(s * s));
    __half hi = __float2half(m);
    __half lo = __float2half(m - __half2float(hi));
    __half* dst = g_restP + (size_t)n * 256;
    dst[c] = hi; dst[128 + c] = lo;
    if (c == 0) g_packed[n] = ~0ull;
}

// ---------------- argmin via ldmatrix + mma.sync, deduped K=256, cp.async pipelined ----------------
// smem: esq(512B) + A 16 chunks x 4KB (64KB) + B 16 chunks x 4KB (64KB)
#define SM_ESQ 0
#define SM_A 512
#define SM_B (512 + 16*4096)
#define SM_TOTAL (512 + 32*4096)

// copy one half (8 k-chunks, 32KB) of code tile starting at code c0; half=0 hi, 1 lo
__device__ __forceinline__ void copyB_half(uint32_t sb, int tid, int c0, int half) {
    #pragma unroll
    for (int j = 0; j < 8; j++) {
        int i = tid + j * 256;                 // uint4 index in [0,2048)
        int chunk = (i >> 8) + half * 8, rr = (i >> 1) & 127, hh = i & 1;
        const char* src = (const char*)g_embP + (size_t)(c0 + rr) * 512 + chunk * 32 + hh * 16;
        uint32_t dst = sb + SM_B + (uint32_t)(chunk * 4096) +
                       (((uint32_t)(rr * 32 + hh * 16)) ^ ((uint32_t)(rr & 7) << 4));
        CP_ASYNC16(dst, src);
    }
}

__global__ __launch_bounds__(256, 1)
void k_argmin_mma(int N, int codesPerBlock) {
    extern __shared__ char smem[];
    uint32_t sb = smem_to_u32(smem);
    float* sEsq = (float*)(smem + SM_ESQ);
    int tid = threadIdx.x;
    int lane = tid & 31, wid = tid >> 5;
    int warp_m = wid >> 2;
    int warp_n = wid & 3;
    int n0 = blockIdx.x * 128;
    int v0 = blockIdx.y * codesPerBlock;
    int nTiles = codesPerBlock >> 7;

    // A stage via cp.async (16 chunks = 64KB; zero-fill rows beyond N), grouped with B_hi(0)
    #pragma unroll
    for (int j = 0; j < 16; j++) {
        int i = tid + j * 256;
        int chunk = i >> 8, rr = (i >> 1) & 127, hh = i & 1;
        int n = n0 + rr;
        const char* src = (const char*)g_restP + (size_t)n * 512 + chunk * 32 + hh * 16;
        uint32_t dst = sb + SM_A + (uint32_t)(chunk * 4096) +
                       (((uint32_t)(rr * 32 + hh * 16)) ^ ((uint32_t)(rr & 7) << 4));
        CP_ASYNC16_P(dst, src, n < N ? 16u : 0u);
    }
    copyB_half(sb, tid, v0, 0);
    CP_COMMIT();

    const float INF = __int_as_float(0x7f800000);
    float best[8];
    int bidx[8];
    #pragma unroll
    for (int i = 0; i < 8; i++) { best[i] = INF; bidx[i] = 0; }

    uint32_t aoff[4], boff[2];
    #pragma unroll
    for (int mf = 0; mf < 4; mf++) {
        int r = warp_m * 64 + mf * 16 + (lane & 15);
        uint32_t off = (uint32_t)(r * 32 + (lane >> 4) * 16);
        aoff[mf] = sb + SM_A + (off ^ ((uint32_t)(r & 7) << 4));
    }
    #pragma unroll
    for (int nf2 = 0; nf2 < 2; nf2++) {
        int n = warp_n * 32 + nf2 * 16 + ((lane >> 4) << 3) + (lane & 7);
        uint32_t off = (uint32_t)(n * 32 + ((lane >> 3) & 1) * 16);
        boff[nf2] = sb + SM_B + (off ^ ((uint32_t)(n & 7) << 4));
    }

    for (int tt = 0; tt < nTiles; tt++) {
        int c0 = v0 + (tt << 7);
        // issue B_lo of current tile (buffer free: prior tile's B_lo readers done at bottom sync)
        copyB_half(sb, tid, c0, 1);
        CP_COMMIT();
        CP_WAIT1();               // B_hi(tt) (+A on tt=0) arrived
        __syncthreads();

        if (tid < 32) {
            float4 e = *(const float4*)(g_esq + c0 + tid * 4);
            *(float4*)(sEsq + tid * 4) = e;
        }

        float acc[4][4][4];
        #pragma unroll
        for (int mf = 0; mf < 4; mf++)
            #pragma unroll
            for (int nf = 0; nf < 4; nf++)
                #pragma unroll
                for (int q = 0; q < 4; q++) acc[mf][nf][q] = 0.f;

        // phase1: seg0 (A_hi * B_hi, k=0..7) + seg1 (A_lo * B_hi, k=8..15)
        #pragma unroll
        for (int k = 0; k < 16; k++) {
            uint32_t acb = (uint32_t)(k * 4096);
            uint32_t bcb = (uint32_t)((k & 7) * 4096);
            uint32_t a[4][4], b[4][2];
            #pragma unroll
            for (int mf = 0; mf < 4; mf++)
                ldsm_x4(a[mf][0], a[mf][1], a[mf][2], a[mf][3], aoff[mf] + acb);
            #pragma unroll
            for (int nf2 = 0; nf2 < 2; nf2++) {
                uint32_t r0, r1, r2, r3;
                ldsm_x4(r0, r1, r2, r3, boff[nf2] + bcb);
                b[nf2*2][0] = r0; b[nf2*2][1] = r1;
                b[nf2*2+1][0] = r2; b[nf2*2+1][1] = r3;
            }
            #pragma unroll
            for (int mf = 0; mf < 4; mf++)
                #pragma unroll
                for (int nf = 0; nf < 4; nf++)
                    mma16816(acc[mf][nf], a[mf], b[nf]);
        }
        __syncthreads();          // all warps done reading B_hi -> safe to overwrite
        if (tt + 1 < nTiles) copyB_half(sb, tid, c0 + 128, 0);
        CP_COMMIT();
        CP_WAIT1();               // B_lo(tt) arrived
        __syncthreads();

        // phase2: seg2 (A_hi * B_lo, k=0..7)
        #pragma unroll
        for (int k = 0; k < 8; k++) {
            uint32_t acb = (uint32_t)(k * 4096);
            uint32_t bcb = (uint32_t)((8 + k) * 4096);
            uint32_t a[4][4], b[4][2];
            #pragma unroll
            for (int mf = 0; mf < 4; mf++)
                ldsm_x4(a[mf][0], a[mf][1], a[mf][2], a[mf][3], aoff[mf] + acb);
            #pragma unroll
            for (int nf2 = 0; nf2 < 2; nf2++) {
                uint32_t r0, r1, r2, r3;
                ldsm_x4(r0, r1, r2, r3, boff[nf2] + bcb);
                b[nf2*2][0] = r0; b[nf2*2][1] = r1;
                b[nf2*2+1][0] = r2; b[nf2*2+1][1] = r3;
            }
            #pragma unroll
            for (int mf = 0; mf < 4; mf++)
                #pragma unroll
                for (int nf = 0; nf < 4; nf++)
                    mma16816(acc[mf][nf], a[mf], b[nf]);
        }

        // epilogue: score + running argmin (strict <, ascending col order)
        #pragma unroll
        for (int nf = 0; nf < 4; nf++) {
            int colL = warp_n * 32 + nf * 8 + 2 * (lane & 3);
            float es0 = sEsq[colL], es1 = sEsq[colL + 1];
            int cg = c0 + colL;
            #pragma unroll
            for (int mf = 0; mf < 4; mf++) {
                float* d = acc[mf][nf];
                int s0 = mf * 2, s1 = mf * 2 + 1;
                float v;
                v = fmaf(-2.f, d[0], es0); if (v < best[s0]) { best[s0] = v; bidx[s0] = cg; }
                v = fmaf(-2.f, d[1], es1); if (v < best[s0]) { best[s0] = v; bidx[s0] = cg + 1; }
                v = fmaf(-2.f, d[2], es0); if (v < best[s1]) { best[s1] = v; bidx[s1] = cg; }
                v = fmaf(-2.f, d[3], es1); if (v < best[s1]) { best[s1] = v; bidx[s1] = cg + 1; }
            }
        }
        __syncthreads();          // B_lo + sEsq readers done before next iter's writes
    }

    #pragma unroll
    for (int o = 1; o <= 2; o <<= 1) {
        #pragma unroll
        for (int s = 0; s < 8; s++) {
            float so = __shfl_xor_sync(0xffffffffu, best[s], o);
            int io = __shfl_xor_sync(0xffffffffu, bidx[s], o);
            if (so < best[s] || (so == best[s] && io < bidx[s])) { best[s] = so; bidx[s] = io; }
        }
    }
    if ((lane & 3) == 0) {
        #pragma unroll
        for (int s = 0; s < 8; s++) {
            int mf = s >> 1, h = s & 1;
            int r = n0 + warp_m * 64 + mf * 16 + (lane >> 2) + h * 8;
            if (r < N) {
                unsigned u = __float_as_uint(best[s]);
                u = (u & 0x80000000u) ? ~u : (u | 0x80000000u);
                unsigned long long p = ((unsigned long long)u << 32) | (unsigned)bidx[s];
                atomicMin(&g_packed[r], p);
            }
        }
    }
}

// ---------------- bicubic weights ----------------
template <int PN>
__device__ __forceinline__ void cubic_weights(int j, float* w) {
    float sf = (j + 0.5f) * ((float)PN / 16.f) - 0.5f;
    float tot = 0.f;
    #pragma unroll
    for (int i = 0; i < PN; i++) {
        float x = fabsf(sf - (float)i);
        float v = 0.f;
        if (x <= 1.f)      v = ((1.5f * x - 2.5f) * x) * x + 1.f;
        else if (x < 2.f)  v = ((-0.5f * x + 2.5f) * x - 4.f) * x + 2.f;
        w[i] = v;
        tot += v;
    }
    float r = 1.f / tot;
    #pragma unroll
    for (int i = 0; i < PN; i++) w[i] *= r;
}

// ---------------- gather + bicubic upsample (also writes hT fp16 split) ----------------
template <int PN>
__global__ void k_upsample(const float* __restrict__ emb) {
    const int NP = PN * PN;
    __shared__ float g[64][128];
    __shared__ float wtab[16][8];
    int b = blockIdx.x;
    for (int i = threadIdx.x; i < NP * CC; i += 256) {
        int p = i >> 7, c = i & 127;
        unsigned idx = (unsigned)(g_packed[b * NP + p] & 0xffffffffu);
        g[p][c] = emb[(size_t)idx * CC + c];
    }
    if (threadIdx.x < 16) cubic_weights<PN>(threadIdx.x, &wtab[threadIdx.x][0]);
    __syncthreads();
    int o0 = blockIdx.y * 8192;
    for (int o = o0 + threadIdx.x; o < o0 + 8192; o += 256) {
        int c = o & 127;
        int sp = o >> 7;
        int x = sp & 15, y = sp >> 4;
        float acc = 0.f;
        #pragma unroll
        for (int iy = 0; iy < PN; iy++) {
            float ra = 0.f;
            #pragma unroll
            for (int ix = 0; ix < PN; ix++)
                ra += wtab[x][ix] * g[iy * PN + ix][c];
            acc += wtab[y][iy] * ra;
        }
        g_h[((size_t)(b * CC + c)) * 256 + y * 16 + x] = acc;
        __half hi = __float2half(acc);
        __half lo = __float2half(acc - __half2float(hi));
        __half* ht = g_hT + ((size_t)b * 256 + sp) * 256;
        ht[c] = hi; ht[128 + c] = lo;
    }
}

__global__ void k_gather16(const float* __restrict__ emb) {
    int n = blockIdx.x;
    int c = threadIdx.x;
    unsigned idx = (unsigned)(g_packed[n] & 0xffffffffu);
    int b = n >> 8, y = (n >> 4) & 15, x = n & 15;
    float v = emb[(size_t)idx * CC + c];
    g_h[((size_t)(b * CC + c)) * 256 + y * 16 + x] = v;
    __half hi = __float2half(v);
    __half lo = __float2half(v - __half2float(hi));
    __half* ht = g_hT + ((size_t)b * 256 + (n & 255)) * 256;
    ht[c] = hi; ht[128 + c] = lo;
}

// ---------------- Phi conv via HMMA + fused residual update / loss / output ----------------
// grid (4 mq, 32 b, 2 cout-half), 256 threads. Block: 64 spatial x 64 couts.
// Iterations grouped by weight chunk; weights staged only on chunk change.
#define SM_IN 0
#define SM_W 13824
#define SM_CONV (13824 + 73728)

__global__ __launch_bounds__(256, 2)
void k_conv_mma(int phi, const float* __restrict__ bias,
                const float* __restrict__ f, float* __restrict__ dout, int is_last) {
    extern __shared__ char smem[];
    uint32_t sb = smem_to_u32(smem);
    int tid = threadIdx.x;
    int lane = tid & 31, wid = tid >> 5;
    int mq = blockIdx.x;
    int b = blockIdx.y;
    int zc = blockIdx.z;
    int warp_m = wid >> 2, warp_n = wid & 3;

    const __half* wSrc = g_wP + (size_t)phi * 9 * 128 * 256;
    const __half* hTb = g_hT + (size_t)b * 256 * 256;

    float acc[2][2][4];
    #pragma unroll
    for (int mf = 0; mf < 2; mf++)
        #pragma unroll
        for (int nf = 0; nf < 2; nf++)
            #pragma unroll
            for (int q = 0; q < 4; q++) acc[mf][nf][q] = 0.f;

    int r0[2];
    #pragma unroll
    for (int mf = 0; mf < 2; mf++) {
        int mloc = warp_m * 32 + mf * 16 + (lane & 15);
        r0[mf] = (mloc >> 4) * 18 + (mloc & 15);
    }
    int acol = (lane >> 4) * 16;
    int nrow = warp_n * 16 + ((lane >> 4) << 3) + (lane & 7);
    int bcol = ((lane >> 3) & 1) * 16;

    const int dts[9] = {0, 1, 2, 18, 19, 20, 36, 37, 38};
    // iteration schedule: (w halfs-offset in [0,256), stage-w?, input plane)
    const int w_offs[6]  = {0, 0, 64, 64, 128, 192};
    const int w_stg[6]   = {1, 0, 1, 0, 1, 1};
    const int in_pln[6]  = {0, 128, 64, 192, 0, 64};

    for (int it = 0; it < 6; it++) {
        int srcPlane = in_pln[it];
        __syncthreads();
        // stage input halo chunk via cp.async (zero-fill OOB): 864 uint4
        #pragma unroll
        for (int j = 0; j < 4; j++) {
            int i = tid + j * 256;
            if (i < 864) {
                int lr = i >> 3, c16 = i & 7;
                int ly = lr / 18, lx = lr - ly * 18;
                int iy = mq * 4 + ly - 1, ix = lx - 1;
                unsigned inb = ((unsigned)iy < 16u && (unsigned)ix < 16u) ? 16u : 0u;
                int spc = ((iy & 15) * 16 + (ix & 15));
                const char* src = (const char*)(hTb + (size_t)spc * 256 + srcPlane + c16 * 8);
                uint32_t dst = sb + SM_IN + (uint32_t)(lr * 128) +
                               (((uint32_t)(c16 * 16)) ^ ((uint32_t)(lr & 7) << 4));
                CP_ASYNC16_P(dst, src, inb);
            }
        }
        // stage 9 taps x 64 couts weight chunk via cp.async (only when chunk changes)
        if (w_stg[it]) {
            int wo = w_offs[it];
            #pragma unroll
            for (int j = 0; j < 18; j++) {
                int i = tid + j * 256;
                int tap = i >> 9, r = (i >> 3) & 63, c16 = i & 7;
                const char* src = (const char*)(wSrc + ((size_t)tap * 128 + zc * 64 + r) * 256 + wo + c16 * 8);
                uint32_t dst = sb + SM_W + (uint32_t)(tap * 8192 + r * 128) +
                               (((uint32_t)(c16 * 16)) ^ ((uint32_t)(r & 7) << 4));
                CP_ASYNC16(dst, src);
            }
        }
        CP_COMMIT();
        CP_WAIT0();
        __syncthreads();

        for (int tap = 0; tap < 9; tap++) {
            int dt = dts[tap];
            uint32_t wbase = sb + SM_W + tap * 8192;
            #pragma unroll
            for (int kb = 0; kb < 4; kb++) {
                uint32_t a[2][4], bf[2][2];
                #pragma unroll
                for (int mf = 0; mf < 2; mf++) {
                    int rA = r0[mf] + dt;
                    uint32_t addr = sb + SM_IN + rA * 128 +
                                    (((uint32_t)(kb * 32 + acol)) ^ ((uint32_t)(rA & 7) << 4));
                    ldsm_x4(a[mf][0], a[mf][1], a[mf][2], a[mf][3], addr);
                }
                {
                    uint32_t addr = wbase + nrow * 128 +
                                    (((uint32_t)(kb * 32 + bcol)) ^ ((uint32_t)(nrow & 7) << 4));
                    uint32_t q0, q1, q2, q3;
                    ldsm_x4(q0, q1, q2, q3, addr);
                    bf[0][0] = q0; bf[0][1] = q1;
                    bf[1][0] = q2; bf[1][1] = q3;
                }
                #pragma unroll
                for (int mf = 0; mf < 2; mf++)
                    #pragma unroll
                    for (int nf = 0; nf < 2; nf++)
                        mma16816(acc[mf][nf], a[mf], bf[nf]);
            }
        }
    }

    // fused epilogue: h2 = 0.5*(h + conv + bias); fhat += h2; frest -= h2;
    // d = fhat - f; SSE; last stage writes straight-through output.
    float sse = 0.f;
    #pragma unroll
    for (int nf = 0; nf < 2; nf++) {
        int c = zc * 64 + warp_n * 16 + nf * 8 + (lane & 3) * 2;
        float bv0 = __ldg(&bias[c]), bv1 = __ldg(&bias[c + 1]);
        #pragma unroll
        for (int mf = 0; mf < 2; mf++) {
            #pragma unroll
            for (int h = 0; h < 2; h++) {
                int m = warp_m * 32 + mf * 16 + (lane >> 2) + h * 8;
                int sp = mq * 64 + m;
                size_t i0 = ((size_t)(b * CC + c)) * 256 + sp;
                size_t i1 = i0 + 256;
                float h20 = 0.5f * (g_h[i0] + acc[mf][nf][h * 2] + bv0);
                float h21 = 0.5f * (g_h[i1] + acc[mf][nf][h * 2 + 1] + bv1);
                float fh0 = g_fhat[i0] + h20;
                float fh1 = g_fhat[i1] + h21;
                g_fhat[i0] = fh0; g_fhat[i1] = fh1;
                g_frest[i0] -= h20; g_frest[i1] -= h21;
                float fv0 = f[i0], fv1 = f[i1];
                float d0 = fh0 - fv0, d1 = fh1 - fv1;
                if (is_last) { dout[i0] = d0 + fv0; dout[i1] = d1 + fv1; }
                sse += d0 * d0 + d1 * d1;
            }
        }
    }
    #pragma unroll
    for (int o = 16; o; o >>= 1) sse += __shfl_xor_sync(0xffffffffu, sse, o);
    __shared__ float ws[8];
    if (lane == 0) ws[wid] = sse;
    __syncthreads();
    if (tid == 0) {
        float t = 0.f;
        #pragma unroll
        for (int k = 0; k < 8; k++) t += ws[k];
        atomicAdd(&g_loss, t);
    }
}

__global__ void k_final(float* dout, int out_size) {
    dout[out_size - 1] = g_loss * (1.25f / (5.f * (float)NUMEL));
}

// ---------------- host ----------------
extern "C" void kernel_launch(void* const* d_in, const int* in_sizes, int n_in,
                              void* d_out, int out_size) {
    const float* f     = (const float*)d_in[0];
    const float* emb   = (const float*)d_in[1];
    const float* phi_w = (const float*)d_in[2];
    const float* phi_b = (const float*)d_in[3];
    float* out = (float*)d_out;

    cudaFuncSetAttribute(k_argmin_mma, cudaFuncAttributeMaxDynamicSharedMemorySize, SM_TOTAL);
    cudaFuncSetAttribute(k_conv_mma, cudaFuncAttributeMaxDynamicSharedMemorySize, SM_CONV);

    // Replicate np.linspace(1/12, 11/12, 4) + argmin(|ticks - si/4|) in double.
    double start = 1.0 / 12.0;
    double stop = 1.0 - 1.0 / 12.0;
    double step = (stop - start) / 3.0;
    double ticks[4];
    ticks[0] = 0.0 * step + start;
    ticks[1] = 1.0 * step + start;
    ticks[2] = 2.0 * step + start;
    ticks[3] = stop;
    int kphi[5];
    for (int si = 0; si < 5; si++) {
        double t = (double)si / 4.0;
        int bi = 0;
        double bd = fabs(ticks[0] - t);
        for (int k = 1; k < 4; k++) {
            double d = fabs(ticks[k] - t);
            if (d < bd) { bd = d; bi = k; }
        }
        kphi[si] = bi;
    }

    const int pns[5]    = {1, 2, 4, 8, 16};
    const int vsplit[5] = {64, 64, 32, 8, 2};

    k_prep_emb<<<VV / 8, 256>>>(emb);
    k_prep_w<<<4 * 9 * 128, 128>>>(phi_w);
    k_init<<<NUMEL / 256, 256>>>(f);

    for (int si = 0; si < 5; si++) {
        int pn = pns[si];
        int s = 16 / pn;
        int N = BB * pn * pn;

        if (s >= 8) {
            int ls = (s == 16) ? 4 : 3;
            k_pool_warp<<<(N * 128) / 8, 256>>>(pn, s, ls, 1.f / (float)(s * s));
        } else {
            k_pool<<<N, 128>>>(pn, s, N);
        }

        int rb = (N + 127) / 128;
        dim3 grd(rb, vsplit[si]);
        k_argmin_mma<<<grd, 256, SM_TOTAL>>>(N, VV / vsplit[si]);

        if (si < 4) {
            dim3 ug(32, 4);
            switch (pn) {
                case 1: k_upsample<1><<<ug, 256>>>(emb); break;
                case 2: k_upsample<2><<<ug, 256>>>(emb); break;
                case 4: k_upsample<4><<<ug, 256>>>(emb); break;
                case 8: k_upsample<8><<<ug, 256>>>(emb); break;
            }
        } else {
            k_gather16<<<VV, 128>>>(emb);
        }

        k_conv_mma<<<dim3(4, 32, 2), 256, SM_CONV>>>(kphi[si], phi_b + kphi[si] * 128,
                                                     f, out, si == 4 ? 1 : 0);
    }

    k_final<<<1, 1>>>(out, out_size);
}

// round 16
// speedup vs baseline: 1.4433x; 1.4433x over previous
#include <cuda_runtime.h>
#include <cuda_fp16.h>
#include <cstdint>
#include <math.h>

// Problem constants
#define BB 32
#define CC 128
#define VV 8192
#define NUMEL (BB*CC*16*16)   // 1048576

// ---------------- device scratch (no allocs allowed) ----------------
__device__ float g_frest[NUMEL];
__device__ float g_fhat[NUMEL];
__device__ float g_esq[VV];
__device__ unsigned long long g_packed[VV]; // (ordered_score<<32)|idx
__device__ float g_h[NUMEL];
__device__ float g_loss;
// fp16 split operands for argmin, K=384:
//   emb:  [hi|hi|lo]   rest: [hi|lo|hi]   -> dot = hi*hi + lo*hi + hi*lo
__device__ __align__(16) __half g_embP[(size_t)VV * 384];
__device__ __align__(16) __half g_restP[(size_t)VV * 384];
// conv operands:
//  hT[b][sp=y*16+x][plane]: plane<128 = hi(h[ci]), 128..255 = lo(h[ci])
__device__ __align__(16) __half g_hT[(size_t)BB * 256 * 256];
//  wP[phi][tap][cout][384]: [hi|hi|lo]
__device__ __align__(16) __half g_wP[(size_t)4 * 9 * 128 * 384];

__device__ __forceinline__ uint32_t smem_to_u32(const void* p) {
    uint32_t a;
    asm("{ .reg .u64 t; cvta.to.shared.u64 t, %1; cvt.u32.u64 %0, t; }" : "=r"(a) : "l"(p));
    return a;
}
__device__ __forceinline__ void ldsm_x4(uint32_t& r0, uint32_t& r1, uint32_t& r2, uint32_t& r3,
                                        uint32_t addr) {
    asm volatile("ldmatrix.sync.aligned.m8n8.x4.shared.b16 {%0,%1,%2,%3}, [%4];"
                 : "=r"(r0), "=r"(r1), "=r"(r2), "=r"(r3) : "r"(addr));
}
__device__ __forceinline__ void mma16816(float* d, const uint32_t* a, const uint32_t* b) {
    asm volatile("mma.sync.aligned.m16n8k16.row.col.f32.f16.f16.f32 "
                 "{%0,%1,%2,%3}, {%4,%5,%6,%7}, {%8,%9}, {%0,%1,%2,%3};"
                 : "+f"(d[0]), "+f"(d[1]), "+f"(d[2]), "+f"(d[3])
                 : "r"(a[0]), "r"(a[1]), "r"(a[2]), "r"(a[3]), "r"(b[0]), "r"(b[1]));
}
#define CP_ASYNC16(dst, src) \
    asm volatile("cp.async.cg.shared.global [%0], [%1], 16;" :: "r"(dst), "l"(src))
#define CP_ASYNC16_P(dst, src, sz) \
    asm volatile("cp.async.cg.shared.global [%0], [%1], 16, %2;" :: "r"(dst), "l"(src), "r"(sz))
#define CP_COMMIT() asm volatile("cp.async.commit_group;" ::: "memory")
#define CP_WAIT1()  asm volatile("cp.async.wait_group 1;" ::: "memory")
#define CP_WAIT0()  asm volatile("cp.async.wait_group 0;" ::: "memory")

// ---------------- init ----------------
__global__ void k_init(const float* __restrict__ f) {
    int i = blockIdx.x * 256 + threadIdx.x;
    g_frest[i] = f[i];
    g_fhat[i] = 0.f;
    if (i == 0) g_loss = 0.f;
}

// ---------------- prep emb: esq + fp16 split [hi|hi|lo] ----------------
__global__ void k_prep_emb(const float* __restrict__ emb) {
    int code = blockIdx.x * 8 + (threadIdx.x >> 5);
    int lane = threadIdx.x & 31;
    float4 v = *(const float4*)(emb + (size_t)code * CC + lane * 4);
    float s = v.x*v.x + v.y*v.y + v.z*v.z + v.w*v.w;
    #pragma unroll
    for (int o = 16; o; o >>= 1) s += __shfl_xor_sync(0xffffffffu, s, o);
    if (lane == 0) g_esq[code] = s;

    __half h0 = __float2half(v.x), h1 = __float2half(v.y);
    __half h2 = __float2half(v.z), h3 = __float2half(v.w);
    __half l0 = __float2half(v.x - __half2float(h0));
    __half l1 = __float2half(v.y - __half2float(h1));
    __half l2 = __float2half(v.z - __half2float(h2));
    __half l3 = __float2half(v.w - __half2float(h3));
    __half2 hA = __halves2half2(h0, h1), hB = __halves2half2(h2, h3);
    __half2 lA = __halves2half2(l0, l1), lB = __halves2half2(l2, l3);
    __half2* base = (__half2*)(g_embP + (size_t)code * 384);
    int c2 = lane * 2;
    base[c2] = hA; base[c2 + 1] = hB;
    base[64 + c2] = hA; base[64 + c2 + 1] = hB;
    base[128 + c2] = lA; base[128 + c2 + 1] = lB;
}

// ---------------- prep weights: wP[phi][tap][cout][384] fp16 [hi|hi|lo] ----------------
__global__ void k_prep_w(const float* __restrict__ phi_w) {
    int id = blockIdx.x;            // 4*9*128
    int cout = id & 127;
    int tap = (id >> 7) % 9;
    int phi = id / (9 * 128);
    int ci = threadIdx.x;
    float w = phi_w[(((size_t)phi * 128 + cout) * 128 + ci) * 9 + tap];
    __half hi = __float2half(w);
    __half lo = __float2half(w - __half2float(hi));
    __half* dst = g_wP + (((size_t)phi * 9 + tap) * 128 + cout) * 384;
    dst[ci] = hi; dst[128 + ci] = hi; dst[256 + ci] = lo;
}

// ---------------- pool (warp-per-output, for s>=8, float4 loads) ----------------
__global__ void k_pool_warp(int pn, int s, int ls2, float inv) {
    int w = (blockIdx.x * 256 + threadIdx.x) >> 5;  // w = n*128 + c
    int lane = threadIdx.x & 31;
    int n = w >> 7, c = w & 127;
    int pp = pn * pn;
    int b = n / pp;
    int rem = n - b * pp;
    int py = rem / pn, px = rem - py * pn;
    const float4* base = (const float4*)(g_frest + ((size_t)(b * CC + c)) * 256 +
                                         (py * s) * 16 + px * s);
    int s4 = s >> 2;           // float4s per row
    int t4 = s * s4;           // total float4s
    float sum = 0.f;
    for (int e = lane; e < t4; e += 32) {
        int r = e >> ls2, cc = e & (s4 - 1);
        float4 v = base[r * 4 + cc];
        sum += v.x + v.y + v.z + v.w;
    }
    #pragma unroll
    for (int o = 16; o; o >>= 1) sum += __shfl_xor_sync(0xffffffffu, sum, o);
    if (lane == 0) {
        float m = sum * inv;
        __half hi = __float2half(m);
        __half lo = __float2half(m - __half2float(hi));
        __half* dst = g_restP + (size_t)n * 384;
        dst[c] = hi; dst[128 + c] = lo; dst[256 + c] = hi;
        if (c == 0) g_packed[n] = ~0ull;
    }
}

// ---------------- pool (thread-per-output, for s<=4) ----------------
__global__ void k_pool(int pn, int s, int N) {
    int n = blockIdx.x;
    int c = threadIdx.x;
    int b = n / (pn * pn);
    int rem = n - b * pn * pn;
    int py = rem / pn, px = rem - py * pn;
    const float* base = g_frest + ((size_t)(b * CC + c)) * 256;
    float sum = 0.f;
    for (int dy = 0; dy < s; dy++)
        for (int dx = 0; dx < s; dx++)
            sum += base[(py * s + dy) * 16 + (px * s + dx)];
    float m = sum * (1.f / (float)(s * s));
    __half hi = __float2half(m);
    __half lo = __float2half(m - __half2float(hi));
    __half* dst = g_restP + (size_t)n * 384;
    dst[c] = hi; dst[128 + c] = lo; dst[256 + c] = hi;
    if (c == 0) g_packed[n] = ~0ull;
}

// ---------------- argmin via ldmatrix + mma.sync, cp.async half-pipelined ----------------
#define SM_ESQ 0
#define SM_A 512
#define SM_B (512 + 24*4096)
#define SM_TOTAL (512 + 48*4096)

// copy one half (12 k-chunks, 48KB) of code tile starting at code c0
__device__ __forceinline__ void copyB_half(char* smem, int tid, int c0, int half) {
    #pragma unroll
    for (int j = 0; j < 12; j++) {
        int i = tid + j * 256 + half * 3072;   // uint4 index in [0,6144)
        int chunk = i >> 8, rr = (i >> 1) & 127, hh = i & 1;
        const char* src = (const char*)g_embP + (size_t)(c0 + rr) * 768 + chunk * 32 + hh * 16;
        uint32_t dst = smem_to_u32(smem) + SM_B + (uint32_t)(chunk * 4096) +
                       (((uint32_t)(rr * 32 + hh * 16)) ^ ((uint32_t)(rr & 7) << 4));
        CP_ASYNC16(dst, src);
    }
}

__global__ __launch_bounds__(256, 1)
void k_argmin_mma(int N, int codesPerBlock) {
    extern __shared__ char smem[];
    uint32_t sb = smem_to_u32(smem);
    float* sEsq = (float*)(smem + SM_ESQ);
    int tid = threadIdx.x;
    int lane = tid & 31, wid = tid >> 5;
    int warp_m = wid >> 2;
    int warp_n = wid & 3;
    int n0 = blockIdx.x * 128;
    int v0 = blockIdx.y * codesPerBlock;
    int nTiles = codesPerBlock >> 7;

    // A stage via cp.async (zero-fill rows beyond N); grouped with first B half
    #pragma unroll
    for (int j = 0; j < 24; j++) {
        int i = tid + j * 256;
        int chunk = i >> 8, rr = (i >> 1) & 127, half = i & 1;
        int n = n0 + rr;
        const char* src = (const char*)g_restP + (size_t)n * 768 + chunk * 32 + half * 16;
        uint32_t dst = sb + SM_A + (uint32_t)(chunk * 4096) +
                       (((uint32_t)(rr * 32 + half * 16)) ^ ((uint32_t)(rr & 7) << 4));
        CP_ASYNC16_P(dst, src, n < N ? 16u : 0u);
    }
    copyB_half(smem, tid, v0, 0);
    CP_COMMIT();

    const float INF = __int_as_float(0x7f800000);
    float best[8];
    int bidx[8];
    #pragma unroll
    for (int i = 0; i < 8; i++) { best[i] = INF; bidx[i] = 0; }

    uint32_t aoff[4], boff[2];
    #pragma unroll
    for (int mf = 0; mf < 4; mf++) {
        int r = warp_m * 64 + mf * 16 + (lane & 15);
        uint32_t off = (uint32_t)(r * 32 + (lane >> 4) * 16);
        aoff[mf] = sb + SM_A + (off ^ ((uint32_t)(r & 7) << 4));
    }
    #pragma unroll
    for (int nf2 = 0; nf2 < 2; nf2++) {
        int n = warp_n * 32 + nf2 * 16 + ((lane >> 4) << 3) + (lane & 7);
        uint32_t off = (uint32_t)(n * 32 + ((lane >> 3) & 1) * 16);
        boff[nf2] = sb + SM_B + (off ^ ((uint32_t)(n & 7) << 4));
    }

    for (int tt = 0; tt < nTiles; tt++) {
        int c0 = v0 + (tt << 7);
        // issue H1 of current tile (H1 buffer free: prior tile's H1 readers done at bottom sync)
        copyB_half(smem, tid, c0, 1);
        CP_COMMIT();
        CP_WAIT1();               // H0(tt) (+A on tt=0) arrived
        __syncthreads();

        if (tid < 32) {
            float4 e = *(const float4*)(g_esq + c0 + tid * 4);
            *(float4*)(sEsq + tid * 4) = e;
        }

        float acc[4][4][4];
        #pragma unroll
        for (int mf = 0; mf < 4; mf++)
            #pragma unroll
            for (int nf = 0; nf < 4; nf++)
                #pragma unroll
                for (int q = 0; q < 4; q++) acc[mf][nf][q] = 0.f;

        // compute on H0 (kc 0..11)
        #pragma unroll
        for (int kc = 0; kc < 12; kc++) {
            uint32_t cb = (uint32_t)(kc * 4096);
            uint32_t a[4][4], b[4][2];
            #pragma unroll
            for (int mf = 0; mf < 4; mf++)
                ldsm_x4(a[mf][0], a[mf][1], a[mf][2], a[mf][3], aoff[mf] + cb);
            #pragma unroll
            for (int nf2 = 0; nf2 < 2; nf2++) {
                uint32_t r0, r1, r2, r3;
                ldsm_x4(r0, r1, r2, r3, boff[nf2] + cb);
                b[nf2*2][0] = r0; b[nf2*2][1] = r1;
                b[nf2*2+1][0] = r2; b[nf2*2+1][1] = r3;
            }
            #pragma unroll
            for (int mf = 0; mf < 4; mf++)
                #pragma unroll
                for (int nf = 0; nf < 4; nf++)
                    mma16816(acc[mf][nf], a[mf], b[nf]);
        }
        __syncthreads();          // all warps done reading H0 -> safe to overwrite
        if (tt + 1 < nTiles) copyB_half(smem, tid, c0 + 128, 0);
        CP_COMMIT();
        CP_WAIT1();               // H1(tt) arrived
        __syncthreads();

        // compute on H1 (kc 12..23)
        #pragma unroll
        for (int kc = 12; kc < 24; kc++) {
            uint32_t cb = (uint32_t)(kc * 4096);
            uint32_t a[4][4], b[4][2];
            #pragma unroll
            for (int mf = 0; mf < 4; mf++)
                ldsm_x4(a[mf][0], a[mf][1], a[mf][2], a[mf][3], aoff[mf] + cb);
            #pragma unroll
            for (int nf2 = 0; nf2 < 2; nf2++) {
                uint32_t r0, r1, r2, r3;
                ldsm_x4(r0, r1, r2, r3, boff[nf2] + cb);
                b[nf2*2][0] = r0; b[nf2*2][1] = r1;
                b[nf2*2+1][0] = r2; b[nf2*2+1][1] = r3;
            }
            #pragma unroll
            for (int mf = 0; mf < 4; mf++)
                #pragma unroll
                for (int nf = 0; nf < 4; nf++)
                    mma16816(acc[mf][nf], a[mf], b[nf]);
        }

        // epilogue: score + running argmin (strict <, ascending col order)
        #pragma unroll
        for (int nf = 0; nf < 4; nf++) {
            int colL = warp_n * 32 + nf * 8 + 2 * (lane & 3);
            float es0 = sEsq[colL], es1 = sEsq[colL + 1];
            int cg = c0 + colL;
            #pragma unroll
            for (int mf = 0; mf < 4; mf++) {
                float* d = acc[mf][nf];
                int s0 = mf * 2, s1 = mf * 2 + 1;
                float v;
                v = fmaf(-2.f, d[0], es0); if (v < best[s0]) { best[s0] = v; bidx[s0] = cg; }
                v = fmaf(-2.f, d[1], es1); if (v < best[s0]) { best[s0] = v; bidx[s0] = cg + 1; }
                v = fmaf(-2.f, d[2], es0); if (v < best[s1]) { best[s1] = v; bidx[s1] = cg; }
                v = fmaf(-2.f, d[3], es1); if (v < best[s1]) { best[s1] = v; bidx[s1] = cg + 1; }
            }
        }
        __syncthreads();          // H1 + sEsq readers done before next iter's writes
    }

    #pragma unroll
    for (int o = 1; o <= 2; o <<= 1) {
        #pragma unroll
        for (int s = 0; s < 8; s++) {
            float so = __shfl_xor_sync(0xffffffffu, best[s], o);
            int io = __shfl_xor_sync(0xffffffffu, bidx[s], o);
            if (so < best[s] || (so == best[s] && io < bidx[s])) { best[s] = so; bidx[s] = io; }
        }
    }
    if ((lane & 3) == 0) {
        #pragma unroll
        for (int s = 0; s < 8; s++) {
            int mf = s >> 1, h = s & 1;
            int r = n0 + warp_m * 64 + mf * 16 + (lane >> 2) + h * 8;
            if (r < N) {
                unsigned u = __float_as_uint(best[s]);
                u = (u & 0x80000000u) ? ~u : (u | 0x80000000u);
                unsigned long long p = ((unsigned long long)u << 32) | (unsigned)bidx[s];
                atomicMin(&g_packed[r], p);
            }
        }
    }
}

// ---------------- bicubic weights ----------------
template <int PN>
__device__ __forceinline__ void cubic_weights(int j, float* w) {
    float sf = (j + 0.5f) * ((float)PN / 16.f) - 0.5f;
    float tot = 0.f;
    #pragma unroll
    for (int i = 0; i < PN; i++) {
        float x = fabsf(sf - (float)i);
        float v = 0.f;
        if (x <= 1.f)      v = ((1.5f * x - 2.5f) * x) * x + 1.f;
        else if (x < 2.f)  v = ((-0.5f * x + 2.5f) * x - 4.f) * x + 2.f;
        w[i] = v;
        tot += v;
    }
    float r = 1.f / tot;
    #pragma unroll
    for (int i = 0; i < PN; i++) w[i] *= r;
}

// ---------------- gather + bicubic upsample (also writes hT fp16 split) ----------------
template <int PN>
__global__ void k_upsample(const float* __restrict__ emb) {
    const int NP = PN * PN;
    __shared__ float g[64][128];
    __shared__ float wtab[16][8];
    int b = blockIdx.x;
    for (int i = threadIdx.x; i < NP * CC; i += 256) {
        int p = i >> 7, c = i & 127;
        unsigned idx = (unsigned)(g_packed[b * NP + p] & 0xffffffffu);
        g[p][c] = emb[(size_t)idx * CC + c];
    }
    if (threadIdx.x < 16) cubic_weights<PN>(threadIdx.x, &wtab[threadIdx.x][0]);
    __syncthreads();
    int o0 = blockIdx.y * 8192;
    for (int o = o0 + threadIdx.x; o < o0 + 8192; o += 256) {
        int c = o & 127;
        int sp = o >> 7;
        int x = sp & 15, y = sp >> 4;
        float acc = 0.f;
        #pragma unroll
        for (int iy = 0; iy < PN; iy++) {
            float ra = 0.f;
            #pragma unroll
            for (int ix = 0; ix < PN; ix++)
                ra += wtab[x][ix] * g[iy * PN + ix][c];
            acc += wtab[y][iy] * ra;
        }
        g_h[((size_t)(b * CC + c)) * 256 + y * 16 + x] = acc;
        __half hi = __float2half(acc);
        __half lo = __float2half(acc - __half2float(hi));
        __half* ht = g_hT + ((size_t)b * 256 + sp) * 256;
        ht[c] = hi; ht[128 + c] = lo;
    }
}

__global__ void k_gather16(const float* __restrict__ emb) {
    int n = blockIdx.x;
    int c = threadIdx.x;
    unsigned idx = (unsigned)(g_packed[n] & 0xffffffffu);
    int b = n >> 8, y = (n >> 4) & 15, x = n & 15;
    float v = emb[(size_t)idx * CC + c];
    g_h[((size_t)(b * CC + c)) * 256 + y * 16 + x] = v;
    __half hi = __float2half(v);
    __half lo = __float2half(v - __half2float(hi));
    __half* ht = g_hT + ((size_t)b * 256 + (n & 255)) * 256;
    ht[c] = hi; ht[128 + c] = lo;
}

// ---------------- Phi conv via HMMA + fused residual update / loss / output ----------------
#define SM_IN 0
#define SM_W 13824
#define SM_CONV (13824 + 73728)

__global__ __launch_bounds__(256, 2)
void k_conv_mma(int phi, const float* __restrict__ bias,
                const float* __restrict__ f, float* __restrict__ dout, int is_last) {
    extern __shared__ char smem[];
    uint32_t sb = smem_to_u32(smem);
    int tid = threadIdx.x;
    int lane = tid & 31, wid = tid >> 5;
    int mq = blockIdx.x;
    int b = blockIdx.y;
    int zc = blockIdx.z;
    int warp_m = wid >> 2, warp_n = wid & 3;

    const __half* wSrc = g_wP + (size_t)phi * 9 * 128 * 384;
    const __half* hTb = g_hT + (size_t)b * 256 * 256;

    float acc[2][2][4];
    #pragma unroll
    for (int mf = 0; mf < 2; mf++)
        #pragma unroll
        for (int nf = 0; nf < 2; nf++)
            #pragma unroll
            for (int q = 0; q < 4; q++) acc[mf][nf][q] = 0.f;

    int r0[2];
    #pragma unroll
    for (int mf = 0; mf < 2; mf++) {
        int mloc = warp_m * 32 + mf * 16 + (lane & 15);
        r0[mf] = (mloc >> 4) * 18 + (mloc & 15);
    }
    int acol = (lane >> 4) * 16;
    int nrow = warp_n * 16 + ((lane >> 4) << 3) + (lane & 7);
    int bcol = ((lane >> 3) & 1) * 16;

    const int dts[9] = {0, 1, 2, 18, 19, 20, 36, 37, 38};

    for (int kc = 0; kc < 6; kc++) {
        int srcPlane = (kc < 4 ? kc : kc - 4) * 64;
        __syncthreads();
        // stage input halo chunk via cp.async (zero-fill OOB): 864 uint4
        #pragma unroll
        for (int j = 0; j < 4; j++) {
            int i = tid + j * 256;
            if (i < 864) {
                int lr = i >> 3, c16 = i & 7;
                int ly = lr / 18, lx = lr - ly * 18;
                int iy = mq * 4 + ly - 1, ix = lx - 1;
                unsigned inb = ((unsigned)iy < 16u && (unsigned)ix < 16u) ? 16u : 0u;
                int spc = ((iy & 15) * 16 + (ix & 15));
                const char* src = (const char*)(hTb + (size_t)spc * 256 + srcPlane + c16 * 8);
                uint32_t dst = sb + SM_IN + (uint32_t)(lr * 128) +
                               (((uint32_t)(c16 * 16)) ^ ((uint32_t)(lr & 7) << 4));
                CP_ASYNC16_P(dst, src, inb);
            }
        }
        // stage 9 taps x 64 couts weight chunk via cp.async: 4608 uint4
        #pragma unroll
        for (int j = 0; j < 18; j++) {
            int i = tid + j * 256;
            int tap = i >> 9, r = (i >> 3) & 63, c16 = i & 7;
            const char* src = (const char*)(wSrc + ((size_t)tap * 128 + zc * 64 + r) * 384 + kc * 64 + c16 * 8);
            uint32_t dst = sb + SM_W + (uint32_t)(tap * 8192 + r * 128) +
                           (((uint32_t)(c16 * 16)) ^ ((uint32_t)(r & 7) << 4));
            CP_ASYNC16(dst, src);
        }
        CP_COMMIT();
        CP_WAIT0();
        __syncthreads();

        for (int tap = 0; tap < 9; tap++) {
            int dt = dts[tap];
            uint32_t wbase = sb + SM_W + tap * 8192;
            #pragma unroll
            for (int kb = 0; kb < 4; kb++) {
                uint32_t a[2][4], bf[2][2];
                #pragma unroll
                for (int mf = 0; mf < 2; mf++) {
                    int rA = r0[mf] + dt;
                    uint32_t addr = sb + SM_IN + rA * 128 +
                                    (((uint32_t)(kb * 32 + acol)) ^ ((uint32_t)(rA & 7) << 4));
                    ldsm_x4(a[mf][0], a[mf][1], a[mf][2], a[mf][3], addr);
                }
                {
                    uint32_t addr = wbase + nrow * 128 +
                                    (((uint32_t)(kb * 32 + bcol)) ^ ((uint32_t)(nrow & 7) << 4));
                    uint32_t q0, q1, q2, q3;
                    ldsm_x4(q0, q1, q2, q3, addr);
                    bf[0][0] = q0; bf[0][1] = q1;
                    bf[1][0] = q2; bf[1][1] = q3;
                }
                #pragma unroll
                for (int mf = 0; mf < 2; mf++)
                    #pragma unroll
                    for (int nf = 0; nf < 2; nf++)
                        mma16816(acc[mf][nf], a[mf], bf[nf]);
            }
        }
    }

    // fused epilogue: h2 = 0.5*(h + conv + bias); fhat += h2; frest -= h2;
    // d = fhat - f; SSE; last stage writes straight-through output.
    float sse = 0.f;
    #pragma unroll
    for (int nf = 0; nf < 2; nf++) {
        int c = zc * 64 + warp_n * 16 + nf * 8 + (lane & 3) * 2;
        float bv0 = __ldg(&bias[c]), bv1 = __ldg(&bias[c + 1]);
        #pragma unroll
        for (int mf = 0; mf < 2; mf++) {
            #pragma unroll
            for (int h = 0; h < 2; h++) {
                int m = warp_m * 32 + mf * 16 + (lane >> 2) + h * 8;
                int sp = mq * 64 + m;
                size_t i0 = ((size_t)(b * CC + c)) * 256 + sp;
                size_t i1 = i0 + 256;
                float h20 = 0.5f * (g_h[i0] + acc[mf][nf][h * 2] + bv0);
                float h21 = 0.5f * (g_h[i1] + acc[mf][nf][h * 2 + 1] + bv1);
                float fh0 = g_fhat[i0] + h20;
                float fh1 = g_fhat[i1] + h21;
                g_fhat[i0] = fh0; g_fhat[i1] = fh1;
                g_frest[i0] -= h20; g_frest[i1] -= h21;
                float fv0 = f[i0], fv1 = f[i1];
                float d0 = fh0 - fv0, d1 = fh1 - fv1;
                if (is_last) { dout[i0] = d0 + fv0; dout[i1] = d1 + fv1; }
                sse += d0 * d0 + d1 * d1;
            }
        }
    }
    #pragma unroll
    for (int o = 16; o; o >>= 1) sse += __shfl_xor_sync(0xffffffffu, sse, o);
    __shared__ float ws[8];
    if (lane == 0) ws[wid] = sse;
    __syncthreads();
    if (tid == 0) {
        float t = 0.f;
        #pragma unroll
        for (int k = 0; k < 8; k++) t += ws[k];
        atomicAdd(&g_loss, t);
    }
}

__global__ void k_final(float* dout, int out_size) {
    dout[out_size - 1] = g_loss * (1.25f / (5.f * (float)NUMEL));
}

// ---------------- host ----------------
extern "C" void kernel_launch(void* const* d_in, const int* in_sizes, int n_in,
                              void* d_out, int out_size) {
    const float* f     = (const float*)d_in[0];
    const float* emb   = (const float*)d_in[1];
    const float* phi_w = (const float*)d_in[2];
    const float* phi_b = (const float*)d_in[3];
    float* out = (float*)d_out;

    cudaFuncSetAttribute(k_argmin_mma, cudaFuncAttributeMaxDynamicSharedMemorySize, SM_TOTAL);
    cudaFuncSetAttribute(k_conv_mma, cudaFuncAttributeMaxDynamicSharedMemorySize, SM_CONV);

    // Replicate np.linspace(1/12, 11/12, 4) + argmin(|ticks - si/4|) in double.
    double start = 1.0 / 12.0;
    double stop = 1.0 - 1.0 / 12.0;
    double step = (stop - start) / 3.0;
    double ticks[4];
    ticks[0] = 0.0 * step + start;
    ticks[1] = 1.0 * step + start;
    ticks[2] = 2.0 * step + start;
    ticks[3] = stop;
    int kphi[5];
    for (int si = 0; si < 5; si++) {
        double t = (double)si / 4.0;
        int bi = 0;
        double bd = fabs(ticks[0] - t);
        for (int k = 1; k < 4; k++) {
            double d = fabs(ticks[k] - t);
            if (d < bd) { bd = d; bi = k; }
        }
        kphi[si] = bi;
    }

    const int pns[5]    = {1, 2, 4, 8, 16};
    const int vsplit[5] = {64, 64, 32, 16, 2};

    k_prep_emb<<<VV / 8, 256>>>(emb);
    k_prep_w<<<4 * 9 * 128, 128>>>(phi_w);
    k_init<<<NUMEL / 256, 256>>>(f);

    for (int si = 0; si < 5; si++) {
        int pn = pns[si];
        int s = 16 / pn;
        int N = BB * pn * pn;

        if (s >= 8) {
            int ls2 = (s == 16) ? 2 : 1;   // log2(s/4)
            k_pool_warp<<<(N * 128) / 8, 256>>>(pn, s, ls2, 1.f / (float)(s * s));
        } else {
            k_pool<<<N, 128>>>(pn, s, N);
        }

        int rb = (N + 127) / 128;
        dim3 grd(rb, vsplit[si]);
        k_argmin_mma<<<grd, 256, SM_TOTAL>>>(N, VV / vsplit[si]);

        if (si < 4) {
            dim3 ug(32, 4);
            switch (pn) {
                case 1: k_upsample<1><<<ug, 256>>>(emb); break;
                case 2: k_upsample<2><<<ug, 256>>>(emb); break;
                case 4: k_upsample<4><<<ug, 256>>>(emb); break;
                case 8: k_upsample<8><<<ug, 256>>>(emb); break;
            }
        } else {
            k_gather16<<<VV, 128>>>(emb);
        }

        k_conv_mma<<<dim3(4, 32, 2), 256, SM_CONV>>>(kphi[si], phi_b + kphi[si] * 128,
                                                     f, out, si == 4 ? 1 : 0);
    }

    k_final<<<1, 1>>>(out, out_size);
}